// round 1
// baseline (speedup 1.0000x reference)
#include <cuda_runtime.h>
#include <math.h>

#define BATCH 8
#define SEQ   4096
#define EMB   768
#define HD    64
#define PAD   68   // shared row stride (floats), multiple of 4 for float4 alignment

// Scratch for q, k, v projections: [B, T, D] fp32 each (8 MB each)
__device__ float g_q[BATCH * SEQ * HD];
__device__ float g_k[BATCH * SEQ * HD];
__device__ float g_v[BATCH * SEQ * HD];

// ---------------------------------------------------------------------------
// Kernel 1: fused QKV projection.
// Each block: 64 rows of x (flattened B*T) x all 64 output dims, K=768 tiled by 64.
// 256 threads, thread (ty,tx) computes a 4x4 tile for each of q, k, v.
// ---------------------------------------------------------------------------
__global__ __launch_bounds__(256) void qkv_kernel(
    const float* __restrict__ x,
    const float* __restrict__ Wq, const float* __restrict__ bq,
    const float* __restrict__ Wk, const float* __restrict__ bk,
    const float* __restrict__ Wv, const float* __restrict__ bv)
{
    extern __shared__ float sm[];
    float* x_sh  = sm;                 // [64][PAD]  x_sh[kk][row]   (transposed)
    float* wq_sh = x_sh  + 64 * PAD;   // [64][PAD]  wq_sh[kk][col]
    float* wk_sh = wq_sh + 64 * PAD;
    float* wv_sh = wk_sh + 64 * PAD;

    const int tid = threadIdx.x;
    const int ty = tid >> 4;         // 0..15 -> query-row group
    const int tx = tid & 15;         // 0..15 -> col group
    const int row0 = blockIdx.x * 64;

    float aq[4][4], ak[4][4], av[4][4];
    #pragma unroll
    for (int c = 0; c < 4; c++) {
        const float bqv = bq[tx * 4 + c];
        const float bkv = bk[tx * 4 + c];
        const float bvv = bv[tx * 4 + c];
        #pragma unroll
        for (int r = 0; r < 4; r++) { aq[r][c] = bqv; ak[r][c] = bkv; av[r][c] = bvv; }
    }

    for (int kt = 0; kt < EMB / 64; kt++) {
        // load x tile (transposed into [kk][row])
        for (int i = tid; i < 64 * 64; i += 256) {
            int r = i >> 6, kk = i & 63;
            x_sh[kk * PAD + r] = x[(size_t)(row0 + r) * EMB + kt * 64 + kk];
        }
        // load W tiles (natural [kk][col])
        for (int i = tid; i < 64 * 64; i += 256) {
            int kk = i >> 6, c = i & 63;
            int gi = (kt * 64 + kk) * HD + c;
            wq_sh[kk * PAD + c] = Wq[gi];
            wk_sh[kk * PAD + c] = Wk[gi];
            wv_sh[kk * PAD + c] = Wv[gi];
        }
        __syncthreads();

        #pragma unroll 8
        for (int kk = 0; kk < 64; kk++) {
            float4 xv = *(const float4*)&x_sh[kk * PAD + ty * 4];
            float4 q4 = *(const float4*)&wq_sh[kk * PAD + tx * 4];
            float4 k4 = *(const float4*)&wk_sh[kk * PAD + tx * 4];
            float4 v4 = *(const float4*)&wv_sh[kk * PAD + tx * 4];
            float xr[4] = {xv.x, xv.y, xv.z, xv.w};
            float qc[4] = {q4.x, q4.y, q4.z, q4.w};
            float kc[4] = {k4.x, k4.y, k4.z, k4.w};
            float vc[4] = {v4.x, v4.y, v4.z, v4.w};
            #pragma unroll
            for (int r = 0; r < 4; r++)
                #pragma unroll
                for (int c = 0; c < 4; c++) {
                    aq[r][c] += xr[r] * qc[c];
                    ak[r][c] += xr[r] * kc[c];
                    av[r][c] += xr[r] * vc[c];
                }
        }
        __syncthreads();
    }

    #pragma unroll
    for (int r = 0; r < 4; r++) {
        size_t o = (size_t)(row0 + ty * 4 + r) * HD + tx * 4;
        *(float4*)&g_q[o] = make_float4(aq[r][0], aq[r][1], aq[r][2], aq[r][3]);
        *(float4*)&g_k[o] = make_float4(ak[r][0], ak[r][1], ak[r][2], ak[r][3]);
        *(float4*)&g_v[o] = make_float4(av[r][0], av[r][1], av[r][2], av[r][3]);
    }
}

// ---------------------------------------------------------------------------
// Kernel 2: causal flash attention, fp32.
// Block = (q-tile qt of 64 queries, batch b). Loops key tiles kt = 0..qt.
// 256 threads; thread (ty,tx): S tile = queries ty*4+[0,4) x keys tx*4+[0,4),
// O tile = queries ty*4+[0,4) x dims tx*4+[0,4). P staged via k_sh (aliased).
// ---------------------------------------------------------------------------
__global__ __launch_bounds__(256) void attn_kernel(float* __restrict__ out)
{
    extern __shared__ float sm[];
    float* q_sh = sm;               // [64][PAD]  q_sh[d][m], pre-scaled by D^-0.5
    float* k_sh = q_sh + 64 * PAD;  // [64][PAD]  k_sh[d][n]; later aliased as p_sh[m][n]
    float* v_sh = k_sh + 64 * PAD;  // [64][PAD]  v_sh[n][d]

    const int tid = threadIdx.x;
    const int ty = tid >> 4;
    const int tx = tid & 15;
    const int qt = blockIdx.x;
    const int b  = blockIdx.y;

    const float* qg = g_q + ((size_t)b * SEQ + qt * 64) * HD;
    const float* kg = g_k + (size_t)b * SEQ * HD;
    const float* vg = g_v + (size_t)b * SEQ * HD;

    // load q tile transposed, pre-scaled
    for (int i = tid; i < 64 * 64; i += 256) {
        int m = i >> 6, d = i & 63;
        q_sh[d * PAD + m] = qg[(size_t)m * HD + d] * 0.125f;  // 64^-0.5
    }

    float O[4][4];
    float mrow[4], lrow[4];
    #pragma unroll
    for (int r = 0; r < 4; r++) {
        mrow[r] = -INFINITY; lrow[r] = 0.f;
        #pragma unroll
        for (int c = 0; c < 4; c++) O[r][c] = 0.f;
    }
    __syncthreads();

    for (int kt = 0; kt <= qt; kt++) {
        // load k (transposed) and v (natural)
        for (int i = tid; i < 64 * 64; i += 256) {
            int n = i >> 6, d = i & 63;
            size_t g = (size_t)(kt * 64 + n) * HD + d;
            k_sh[d * PAD + n] = kg[g];
            v_sh[n * PAD + d] = vg[g];
        }
        __syncthreads();

        // S = (q * scale) @ k^T
        float S[4][4];
        #pragma unroll
        for (int r = 0; r < 4; r++)
            #pragma unroll
            for (int c = 0; c < 4; c++) S[r][c] = 0.f;

        #pragma unroll 16
        for (int d = 0; d < 64; d++) {
            float4 qv = *(const float4*)&q_sh[d * PAD + ty * 4];
            float4 kv = *(const float4*)&k_sh[d * PAD + tx * 4];
            float qa[4] = {qv.x, qv.y, qv.z, qv.w};
            float ka[4] = {kv.x, kv.y, kv.z, kv.w};
            #pragma unroll
            for (int r = 0; r < 4; r++)
                #pragma unroll
                for (int c = 0; c < 4; c++) S[r][c] += qa[r] * ka[c];
        }

        // causal mask (only the diagonal tile needs it)
        if (kt == qt) {
            #pragma unroll
            for (int r = 0; r < 4; r++)
                #pragma unroll
                for (int c = 0; c < 4; c++)
                    if (tx * 4 + c > ty * 4 + r) S[r][c] = -INFINITY;
        }

        // online softmax update
        float alpha[4];
        #pragma unroll
        for (int r = 0; r < 4; r++) {
            float mx = fmaxf(fmaxf(S[r][0], S[r][1]), fmaxf(S[r][2], S[r][3]));
            #pragma unroll
            for (int off = 1; off < 16; off <<= 1)
                mx = fmaxf(mx, __shfl_xor_sync(0xffffffffu, mx, off));
            float mnew = fmaxf(mrow[r], mx);
            alpha[r] = __expf(mrow[r] - mnew);   // exp(-inf)=0 on first tile
            mrow[r] = mnew;

            float sum = 0.f;
            #pragma unroll
            for (int c = 0; c < 4; c++) {
                S[r][c] = __expf(S[r][c] - mnew);
                sum += S[r][c];
            }
            #pragma unroll
            for (int off = 1; off < 16; off <<= 1)
                sum += __shfl_xor_sync(0xffffffffu, sum, off);
            lrow[r] = lrow[r] * alpha[r] + sum;
            #pragma unroll
            for (int c = 0; c < 4; c++) O[r][c] *= alpha[r];
        }

        // stage P through shared (alias k_sh as p_sh[m][n])
        __syncthreads();   // everyone done reading k_sh
        #pragma unroll
        for (int r = 0; r < 4; r++)
            *(float4*)&k_sh[(ty * 4 + r) * PAD + tx * 4] =
                make_float4(S[r][0], S[r][1], S[r][2], S[r][3]);
        __syncthreads();

        // O += P @ V
        #pragma unroll 16
        for (int n = 0; n < 64; n++) {
            float4 vv = *(const float4*)&v_sh[n * PAD + tx * 4];
            float va[4] = {vv.x, vv.y, vv.z, vv.w};
            #pragma unroll
            for (int r = 0; r < 4; r++) {
                float p = k_sh[(ty * 4 + r) * PAD + n];   // broadcast across tx
                #pragma unroll
                for (int c = 0; c < 4; c++) O[r][c] += p * va[c];
            }
        }
        __syncthreads();   // before overwriting k_sh/v_sh next iter
    }

    // epilogue: normalize and write
    #pragma unroll
    for (int r = 0; r < 4; r++) {
        float inv = 1.0f / lrow[r];
        size_t o = ((size_t)b * SEQ + qt * 64 + ty * 4 + r) * HD + tx * 4;
        *(float4*)&out[o] = make_float4(O[r][0] * inv, O[r][1] * inv,
                                        O[r][2] * inv, O[r][3] * inv);
    }
}

extern "C" void kernel_launch(void* const* d_in, const int* in_sizes, int n_in,
                              void* d_out, int out_size)
{
    const float* x  = (const float*)d_in[0];
    const float* Wq = (const float*)d_in[1];
    const float* bq = (const float*)d_in[2];
    const float* Wk = (const float*)d_in[3];
    const float* bk = (const float*)d_in[4];
    const float* Wv = (const float*)d_in[5];
    const float* bv = (const float*)d_in[6];
    float* out = (float*)d_out;

    const int qkv_smem  = 4 * 64 * PAD * sizeof(float);  // 69632
    const int attn_smem = 3 * 64 * PAD * sizeof(float);  // 52224
    cudaFuncSetAttribute(qkv_kernel,  cudaFuncAttributeMaxDynamicSharedMemorySize, qkv_smem);
    cudaFuncSetAttribute(attn_kernel, cudaFuncAttributeMaxDynamicSharedMemorySize, attn_smem);

    qkv_kernel<<<(BATCH * SEQ) / 64, 256, qkv_smem>>>(x, Wq, bq, Wk, bk, Wv, bv);

    dim3 grid(SEQ / 64, BATCH);
    attn_kernel<<<grid, 256, attn_smem>>>(out);
}

// round 2
// speedup vs baseline: 1.7293x; 1.7293x over previous
#include <cuda_runtime.h>
#include <math.h>

#define BATCH 8
#define SEQ   4096
#define EMB   768
#define HD    64
#define PAD   68   // smem row stride in floats

// Scratch for q, k, v projections: [B, T, D] fp32 each
__device__ float g_q[BATCH * SEQ * HD];
__device__ float g_k[BATCH * SEQ * HD];
__device__ float g_v[BATCH * SEQ * HD];

__device__ __forceinline__ unsigned f2tf32(float f) {
    unsigned u;
    asm("cvt.rna.tf32.f32 %0, %1;" : "=r"(u) : "f"(f));
    return u;
}

__device__ __forceinline__ void mma_tf32(float c[4],
                                         unsigned a0, unsigned a1, unsigned a2, unsigned a3,
                                         unsigned b0, unsigned b1) {
    asm("mma.sync.aligned.m16n8k8.row.col.f32.tf32.tf32.f32 "
        "{%0,%1,%2,%3}, {%4,%5,%6,%7}, {%8,%9}, {%0,%1,%2,%3};"
        : "+f"(c[0]), "+f"(c[1]), "+f"(c[2]), "+f"(c[3])
        : "r"(a0), "r"(a1), "r"(a2), "r"(a3), "r"(b0), "r"(b1));
}

// ---------------------------------------------------------------------------
// Kernel 1: fused QKV projection with tf32 MMA.
// Block: 64 rows of x, 384 threads = 12 warps.
// Warp w: row-group rg = w&3 (rows 16*rg..16*rg+15), matrix mat = w>>2 (q/k/v).
// K = 768 processed in 12 chunks of 64.
// ---------------------------------------------------------------------------
__global__ __launch_bounds__(384) void qkv_kernel(
    const float* __restrict__ x,
    const float* __restrict__ Wq, const float* __restrict__ bq,
    const float* __restrict__ Wk, const float* __restrict__ bk,
    const float* __restrict__ Wv, const float* __restrict__ bv)
{
    extern __shared__ float sm[];
    float* x_sh = sm;                 // [64 rows][PAD]  (cols = k-chunk, tf32 bits)
    float* w_sh = x_sh + 64 * PAD;    // [3][64 n][PAD]  (cols = k, transposed, tf32 bits)

    const int tid  = threadIdx.x;
    const int lane = tid & 31;
    const int w    = tid >> 5;
    const int rg   = w & 3;
    const int mat  = w >> 2;          // 0=q, 1=k, 2=v
    const int g    = lane >> 2;       // group (0..7)
    const int tg   = lane & 3;        // thread-in-group (0..3)
    const int row0 = blockIdx.x * 64;

    const float* W = (mat == 0) ? Wq : (mat == 1) ? Wk : Wv;
    const float* bias = (mat == 0) ? bq : (mat == 1) ? bk : bv;
    float* outp = (mat == 0) ? g_q : (mat == 1) ? g_k : g_v;

    float acc[8][4];
    #pragma unroll
    for (int j = 0; j < 8; j++)
        #pragma unroll
        for (int i = 0; i < 4; i++) acc[j][i] = 0.f;

    for (int kt = 0; kt < EMB / 64; kt++) {
        __syncthreads();
        // x tile: [r][c], tf32-rounded
        for (int i = tid; i < 64 * 64; i += 384) {
            int r = i >> 6, c = i & 63;
            x_sh[r * PAD + c] = __uint_as_float(
                f2tf32(x[(size_t)(row0 + r) * EMB + kt * 64 + c]));
        }
        // W tiles transposed: w_sh[m][n][k]
        for (int i = tid; i < 3 * 64 * 64; i += 384) {
            int m = i >> 12, rem = i & 4095;
            int k = rem >> 6, c = rem & 63;
            const float* Wm = (m == 0) ? Wq : (m == 1) ? Wk : Wv;
            w_sh[(m * 64 + c) * PAD + k] = __uint_as_float(
                f2tf32(Wm[(size_t)(kt * 64 + k) * HD + c]));
        }
        __syncthreads();

        // A fragments for this warp's 16 rows, 8 k-steps
        unsigned a[8][4];
        #pragma unroll
        for (int s = 0; s < 8; s++) {
            const float* base = &x_sh[(16 * rg + g) * PAD + s * 8 + tg];
            a[s][0] = __float_as_uint(base[0]);
            a[s][1] = __float_as_uint(base[8 * PAD]);
            a[s][2] = __float_as_uint(base[4]);
            a[s][3] = __float_as_uint(base[8 * PAD + 4]);
        }

        const float* wb = &w_sh[mat * 64 * PAD];
        #pragma unroll
        for (int s = 0; s < 8; s++) {
            #pragma unroll
            for (int j = 0; j < 8; j++) {
                const float* bp = &wb[(j * 8 + g) * PAD + s * 8 + tg];
                unsigned b0 = __float_as_uint(bp[0]);
                unsigned b1 = __float_as_uint(bp[4]);
                mma_tf32(acc[j], a[s][0], a[s][1], a[s][2], a[s][3], b0, b1);
            }
        }
    }

    // epilogue: add bias, write q/k/v
    #pragma unroll
    for (int j = 0; j < 8; j++) {
        int col = j * 8 + 2 * tg;
        float b0 = bias[col], b1 = bias[col + 1];
        int r0 = row0 + 16 * rg + g;
        *(float2*)&outp[(size_t)r0 * HD + col] =
            make_float2(acc[j][0] + b0, acc[j][1] + b1);
        *(float2*)&outp[(size_t)(r0 + 8) * HD + col] =
            make_float2(acc[j][2] + b0, acc[j][3] + b1);
    }
}

// ---------------------------------------------------------------------------
// Kernel 2: causal flash attention with tf32 MMA.
// Block: 64 queries (q-tile) x batch. 128 threads = 4 warps.
// Warp w owns query rows 16w..16w+15. Q fragments live in registers.
// ---------------------------------------------------------------------------
__global__ __launch_bounds__(128) void attn_kernel(float* __restrict__ out)
{
    extern __shared__ float sm[];
    float* k_sh = sm;                 // [64 key][PAD]  K[key][d]   (tf32 bits)
    float* v_sh = k_sh + 64 * PAD;    // [64 dim][PAD]  V^T[d][key] (tf32 bits)
    float* p_sh = v_sh + 64 * PAD;    // [64 q][PAD]    P[q][key]   (tf32 bits, warp-private rows)

    const int tid  = threadIdx.x;
    const int lane = tid & 31;
    const int w    = tid >> 5;        // warp 0..3
    const int g    = lane >> 2;
    const int tg   = lane & 3;
    const int qt   = blockIdx.x;
    const int b    = blockIdx.y;

    const float* qg = g_q + ((size_t)b * SEQ + qt * 64) * HD;
    const float* kg = g_k + (size_t)b * SEQ * HD;
    const float* vg = g_v + (size_t)b * SEQ * HD;

    // Preload Q fragments (rows 16w+g, 16w+g+8), pre-scaled by D^-0.5
    unsigned qa[8][4];
    #pragma unroll
    for (int s = 0; s < 8; s++) {
        const float* base = &qg[(size_t)(16 * w + g) * HD + s * 8 + tg];
        qa[s][0] = f2tf32(base[0] * 0.125f);
        qa[s][1] = f2tf32(base[8 * HD] * 0.125f);
        qa[s][2] = f2tf32(base[4] * 0.125f);
        qa[s][3] = f2tf32(base[8 * HD + 4] * 0.125f);
    }

    float O[8][4];
    #pragma unroll
    for (int j = 0; j < 8; j++)
        #pragma unroll
        for (int i = 0; i < 4; i++) O[j][i] = 0.f;
    float m0 = -INFINITY, m1 = -INFINITY, l0 = 0.f, l1 = 0.f;

    for (int kt = 0; kt <= qt; kt++) {
        __syncthreads();  // previous iteration's reads of k_sh/v_sh done
        for (int i = tid; i < 64 * 64; i += 128) {
            int key = i >> 6, d = i & 63;
            size_t gidx = (size_t)(kt * 64 + key) * HD + d;
            k_sh[key * PAD + d] = __uint_as_float(f2tf32(kg[gidx]));
            v_sh[d * PAD + key] = __uint_as_float(f2tf32(vg[gidx]));
        }
        __syncthreads();

        // S = Qs @ K^T   (m16 x n64, k=64)
        float S[8][4];
        #pragma unroll
        for (int j = 0; j < 8; j++)
            #pragma unroll
            for (int i = 0; i < 4; i++) S[j][i] = 0.f;

        #pragma unroll
        for (int s = 0; s < 8; s++) {
            #pragma unroll
            for (int j = 0; j < 8; j++) {
                const float* bp = &k_sh[(j * 8 + g) * PAD + s * 8 + tg];
                unsigned b0 = __float_as_uint(bp[0]);
                unsigned b1 = __float_as_uint(bp[4]);
                mma_tf32(S[j], qa[s][0], qa[s][1], qa[s][2], qa[s][3], b0, b1);
            }
        }

        // causal mask (diagonal tile only)
        if (kt == qt) {
            int r0 = 16 * w + g, r1 = r0 + 8;
            #pragma unroll
            for (int j = 0; j < 8; j++) {
                int c0 = j * 8 + 2 * tg, c1 = c0 + 1;
                if (c0 > r0) S[j][0] = -INFINITY;
                if (c1 > r0) S[j][1] = -INFINITY;
                if (c0 > r1) S[j][2] = -INFINITY;
                if (c1 > r1) S[j][3] = -INFINITY;
            }
        }

        // online softmax: rows r0 = 16w+g (S[j][0,1]) and r1 = r0+8 (S[j][2,3])
        float tmax0 = -INFINITY, tmax1 = -INFINITY;
        #pragma unroll
        for (int j = 0; j < 8; j++) {
            tmax0 = fmaxf(tmax0, fmaxf(S[j][0], S[j][1]));
            tmax1 = fmaxf(tmax1, fmaxf(S[j][2], S[j][3]));
        }
        tmax0 = fmaxf(tmax0, __shfl_xor_sync(0xffffffffu, tmax0, 1));
        tmax0 = fmaxf(tmax0, __shfl_xor_sync(0xffffffffu, tmax0, 2));
        tmax1 = fmaxf(tmax1, __shfl_xor_sync(0xffffffffu, tmax1, 1));
        tmax1 = fmaxf(tmax1, __shfl_xor_sync(0xffffffffu, tmax1, 2));

        float mn0 = fmaxf(m0, tmax0), mn1 = fmaxf(m1, tmax1);
        float al0 = __expf(m0 - mn0), al1 = __expf(m1 - mn1);
        m0 = mn0; m1 = mn1;

        float rs0 = 0.f, rs1 = 0.f;
        #pragma unroll
        for (int j = 0; j < 8; j++) {
            S[j][0] = __expf(S[j][0] - mn0);
            S[j][1] = __expf(S[j][1] - mn0);
            S[j][2] = __expf(S[j][2] - mn1);
            S[j][3] = __expf(S[j][3] - mn1);
            rs0 += S[j][0] + S[j][1];
            rs1 += S[j][2] + S[j][3];
        }
        rs0 += __shfl_xor_sync(0xffffffffu, rs0, 1);
        rs0 += __shfl_xor_sync(0xffffffffu, rs0, 2);
        rs1 += __shfl_xor_sync(0xffffffffu, rs1, 1);
        rs1 += __shfl_xor_sync(0xffffffffu, rs1, 2);
        l0 = l0 * al0 + rs0;
        l1 = l1 * al1 + rs1;

        #pragma unroll
        for (int j = 0; j < 8; j++) {
            O[j][0] *= al0; O[j][1] *= al0;
            O[j][2] *= al1; O[j][3] *= al1;
        }

        // stage P (tf32) into warp-private smem rows
        int pr0 = 16 * w + g, pr1 = pr0 + 8;
        #pragma unroll
        for (int j = 0; j < 8; j++) {
            int c = j * 8 + 2 * tg;
            p_sh[pr0 * PAD + c]     = __uint_as_float(f2tf32(S[j][0]));
            p_sh[pr0 * PAD + c + 1] = __uint_as_float(f2tf32(S[j][1]));
            p_sh[pr1 * PAD + c]     = __uint_as_float(f2tf32(S[j][2]));
            p_sh[pr1 * PAD + c + 1] = __uint_as_float(f2tf32(S[j][3]));
        }
        __syncwarp();

        // O += P @ V   (A = P m16 x k64, B = V k64 x n64 via v_sh[d][key])
        #pragma unroll
        for (int s = 0; s < 8; s++) {
            const float* pb = &p_sh[(16 * w + g) * PAD + s * 8 + tg];
            unsigned pa0 = __float_as_uint(pb[0]);
            unsigned pa1 = __float_as_uint(pb[8 * PAD]);
            unsigned pa2 = __float_as_uint(pb[4]);
            unsigned pa3 = __float_as_uint(pb[8 * PAD + 4]);
            #pragma unroll
            for (int j = 0; j < 8; j++) {
                const float* bp = &v_sh[(j * 8 + g) * PAD + s * 8 + tg];
                unsigned b0 = __float_as_uint(bp[0]);
                unsigned b1 = __float_as_uint(bp[4]);
                mma_tf32(O[j], pa0, pa1, pa2, pa3, b0, b1);
            }
        }
        __syncwarp();
    }

    // epilogue
    float inv0 = 1.0f / l0, inv1 = 1.0f / l1;
    int r0 = qt * 64 + 16 * w + g;
    #pragma unroll
    for (int j = 0; j < 8; j++) {
        int col = j * 8 + 2 * tg;
        *(float2*)&out[((size_t)b * SEQ + r0) * HD + col] =
            make_float2(O[j][0] * inv0, O[j][1] * inv0);
        *(float2*)&out[((size_t)b * SEQ + r0 + 8) * HD + col] =
            make_float2(O[j][2] * inv1, O[j][3] * inv1);
    }
}

extern "C" void kernel_launch(void* const* d_in, const int* in_sizes, int n_in,
                              void* d_out, int out_size)
{
    const float* x  = (const float*)d_in[0];
    const float* Wq = (const float*)d_in[1];
    const float* bq = (const float*)d_in[2];
    const float* Wk = (const float*)d_in[3];
    const float* bk = (const float*)d_in[4];
    const float* Wv = (const float*)d_in[5];
    const float* bv = (const float*)d_in[6];
    float* out = (float*)d_out;

    const int qkv_smem  = 4 * 64 * PAD * sizeof(float);  // x + 3*W = 69632
    const int attn_smem = 3 * 64 * PAD * sizeof(float);  // k + v + p = 52224
    cudaFuncSetAttribute(qkv_kernel,  cudaFuncAttributeMaxDynamicSharedMemorySize, qkv_smem);
    cudaFuncSetAttribute(attn_kernel, cudaFuncAttributeMaxDynamicSharedMemorySize, attn_smem);

    qkv_kernel<<<(BATCH * SEQ) / 64, 384, qkv_smem>>>(x, Wq, bq, Wk, bk, Wv, bv);

    dim3 grid(SEQ / 64, BATCH);
    attn_kernel<<<grid, 128, attn_smem>>>(out);
}

// round 3
// speedup vs baseline: 3.2933x; 1.9044x over previous
#include <cuda_runtime.h>
#include <math.h>

#define BATCH 8
#define SEQ   4096
#define EMB   768
#define HD    64
#define PAD   68   // smem row stride in floats; (68*4)%16==0 so rows stay 16B-aligned

// Scratch (tf32 bit patterns stored as float):
__device__ float g_q [BATCH * SEQ * HD];          // [b][t][d], pre-scaled by 0.125
__device__ float g_k [BATCH * SEQ * HD];          // [b][t][d]
__device__ float g_vT[BATCH * HD * SEQ];          // [b][d][t]  (transposed V)
__device__ float g_wT[3 * HD * EMB];              // [m][n][k]  (transposed W, tf32)

__device__ __forceinline__ unsigned f2tf32(float f) {
    unsigned u;
    asm("cvt.rna.tf32.f32 %0, %1;" : "=r"(u) : "f"(f));
    return u;
}

__device__ __forceinline__ void mma_tf32(float c[4],
                                         unsigned a0, unsigned a1, unsigned a2, unsigned a3,
                                         unsigned b0, unsigned b1) {
    asm("mma.sync.aligned.m16n8k8.row.col.f32.tf32.tf32.f32 "
        "{%0,%1,%2,%3}, {%4,%5,%6,%7}, {%8,%9}, {%0,%1,%2,%3};"
        : "+f"(c[0]), "+f"(c[1]), "+f"(c[2]), "+f"(c[3])
        : "r"(a0), "r"(a1), "r"(a2), "r"(a3), "r"(b0), "r"(b1));
}

__device__ __forceinline__ void cp16(float* dst, const float* src) {
    unsigned d = (unsigned)__cvta_generic_to_shared(dst);
    asm volatile("cp.async.cg.shared.global [%0], [%1], 16;" :: "r"(d), "l"(src));
}
__device__ __forceinline__ void cp_commit() { asm volatile("cp.async.commit_group;"); }
__device__ __forceinline__ void cp_wait0()  { asm volatile("cp.async.wait_group 0;" ::: "memory"); }

// ---------------------------------------------------------------------------
// Kernel 0: transpose + tf32-convert weights: g_wT[m][n][k]
// ---------------------------------------------------------------------------
__global__ __launch_bounds__(256) void prep_w(
    const float* __restrict__ Wq, const float* __restrict__ Wk, const float* __restrict__ Wv)
{
    int i = blockIdx.x * 256 + threadIdx.x;
    if (i >= 3 * EMB * HD) return;
    int m = i / (EMB * HD);
    int r = (i / HD) % EMB;    // k index
    int c = i & (HD - 1);      // n index (fastest -> coalesced read)
    const float* W = (m == 0) ? Wq : (m == 1) ? Wk : Wv;
    g_wT[(m * HD + c) * EMB + r] = __uint_as_float(f2tf32(W[r * HD + c]));
}

// ---------------------------------------------------------------------------
// Kernel 1: fused QKV projection, tf32 MMA, cp.async double-buffered.
// 384 threads = 12 warps. Warp w: rows 16*(w&3).., matrix (w>>2).
// smem per stage: x[64][PAD] raw fp32 + w[3*64][PAD] tf32.
// ---------------------------------------------------------------------------
__global__ __launch_bounds__(384) void qkv_kernel(
    const float* __restrict__ x,
    const float* __restrict__ bq, const float* __restrict__ bk, const float* __restrict__ bv)
{
    extern __shared__ float sm[];
    const int STAGE = 4 * 64 * PAD;

    const int tid  = threadIdx.x;
    const int lane = tid & 31;
    const int w    = tid >> 5;
    const int rg   = w & 3;
    const int mat  = w >> 2;
    const int g    = lane >> 2;
    const int tg   = lane & 3;
    const int row0 = blockIdx.x * 64;

    const float* bias = (mat == 0) ? bq : (mat == 1) ? bk : bv;

    // issue loads for k-chunk kt into stage st
    auto issue = [&](int kt, int st) {
        float* xs = sm + st * STAGE;
        float* ws = xs + 64 * PAD;
        for (int i = tid; i < 64 * 16; i += 384) {          // x tile: 64 rows x 16 chunks
            int r = i >> 4, q = i & 15;
            cp16(&xs[r * PAD + q * 4], &x[(size_t)(row0 + r) * EMB + kt * 64 + q * 4]);
        }
        for (int i = tid; i < 3 * 64 * 16; i += 384) {      // W tiles (pre-transposed tf32)
            int r = i >> 4, q = i & 15;                     // r = m*64 + n
            cp16(&ws[r * PAD + q * 4], &g_wT[(size_t)r * EMB + kt * 64 + q * 4]);
        }
        cp_commit();
    };

    float acc[8][4];
    #pragma unroll
    for (int j = 0; j < 8; j++)
        #pragma unroll
        for (int i = 0; i < 4; i++) acc[j][i] = 0.f;

    issue(0, 0);
    int st = 0;
    for (int kt = 0; kt < EMB / 64; kt++) {
        cp_wait0();
        __syncthreads();
        if (kt + 1 < EMB / 64) issue(kt + 1, st ^ 1);

        float* xs = sm + st * STAGE;
        float* ws = xs + 64 * PAD + mat * 64 * PAD;

        unsigned a[8][4];
        #pragma unroll
        for (int s = 0; s < 8; s++) {
            const float* base = &xs[(16 * rg + g) * PAD + s * 8 + tg];
            a[s][0] = f2tf32(base[0]);
            a[s][1] = f2tf32(base[8 * PAD]);
            a[s][2] = f2tf32(base[4]);
            a[s][3] = f2tf32(base[8 * PAD + 4]);
        }
        #pragma unroll
        for (int s = 0; s < 8; s++) {
            #pragma unroll
            for (int j = 0; j < 8; j++) {
                const float* bp = &ws[(j * 8 + g) * PAD + s * 8 + tg];
                unsigned b0 = __float_as_uint(bp[0]);
                unsigned b1 = __float_as_uint(bp[4]);
                mma_tf32(acc[j], a[s][0], a[s][1], a[s][2], a[s][3], b0, b1);
            }
        }
        st ^= 1;
    }

    // epilogue: bias, (scale for q), tf32-convert, store
    #pragma unroll
    for (int j = 0; j < 8; j++) {
        int col = j * 8 + 2 * tg;
        float b0 = bias[col], b1 = bias[col + 1];
        int r0 = row0 + 16 * rg + g;
        float v00 = acc[j][0] + b0, v01 = acc[j][1] + b1;
        float v10 = acc[j][2] + b0, v11 = acc[j][3] + b1;
        if (mat == 0) { v00 *= 0.125f; v01 *= 0.125f; v10 *= 0.125f; v11 *= 0.125f; }
        unsigned u00 = f2tf32(v00), u01 = f2tf32(v01);
        unsigned u10 = f2tf32(v10), u11 = f2tf32(v11);
        if (mat == 2) {
            // transposed store: g_vT[b][d][t]
            int b  = r0 >> 12, t = r0 & (SEQ - 1);
            size_t base = ((size_t)b * HD) * SEQ;
            g_vT[base + (size_t)col       * SEQ + t]        = __uint_as_float(u00);
            g_vT[base + (size_t)(col + 1) * SEQ + t]        = __uint_as_float(u01);
            g_vT[base + (size_t)col       * SEQ + t + 8]    = __uint_as_float(u10);
            g_vT[base + (size_t)(col + 1) * SEQ + t + 8]    = __uint_as_float(u11);
        } else {
            float* outp = (mat == 0) ? g_q : g_k;
            *(uint2*)&outp[(size_t)r0 * HD + col]       = make_uint2(u00, u01);
            *(uint2*)&outp[(size_t)(r0 + 8) * HD + col] = make_uint2(u10, u11);
        }
    }
}

// ---------------------------------------------------------------------------
// Kernel 2: causal flash attention, tf32 MMA, cp.async double-buffered K/V.
// 128 threads = 4 warps, 64-query tiles. P staged in the current K buffer.
// ---------------------------------------------------------------------------
__global__ __launch_bounds__(128) void attn_kernel(float* __restrict__ out)
{
    extern __shared__ float sm[];
    const int STAGE = 2 * 64 * PAD;    // k tile + v tile

    const int tid  = threadIdx.x;
    const int lane = tid & 31;
    const int w    = tid >> 5;
    const int g    = lane >> 2;
    const int tg   = lane & 3;
    const int qt   = gridDim.x - 1 - blockIdx.x;   // heaviest tiles first
    const int b    = blockIdx.y;

    const float* qg  = g_q  + ((size_t)b * SEQ + qt * 64) * HD;
    const float* kg  = g_k  + (size_t)b * SEQ * HD;
    const float* vTg = g_vT + (size_t)b * HD * SEQ;

    auto issue = [&](int kt, int stg) {
        float* ks = sm + stg * STAGE;
        float* vs = ks + 64 * PAD;
        for (int i = tid; i < 64 * 16; i += 128) {
            int r = i >> 4, q = i & 15;
            cp16(&ks[r * PAD + q * 4], &kg[(size_t)(kt * 64 + r) * HD + q * 4]);
            cp16(&vs[r * PAD + q * 4], &vTg[(size_t)r * SEQ + kt * 64 + q * 4]);
        }
        cp_commit();
    };

    issue(0, 0);

    // Q fragments (tf32 bits, pre-scaled) straight from global
    const unsigned* qgu = (const unsigned*)qg;
    unsigned qa[8][4];
    #pragma unroll
    for (int s = 0; s < 8; s++) {
        const unsigned* base = &qgu[(size_t)(16 * w + g) * HD + s * 8 + tg];
        qa[s][0] = base[0];
        qa[s][1] = base[8 * HD];
        qa[s][2] = base[4];
        qa[s][3] = base[8 * HD + 4];
    }

    float O[8][4];
    #pragma unroll
    for (int j = 0; j < 8; j++)
        #pragma unroll
        for (int i = 0; i < 4; i++) O[j][i] = 0.f;
    float m0 = -INFINITY, m1 = -INFINITY, l0 = 0.f, l1 = 0.f;

    int st = 0;
    for (int kt = 0; kt <= qt; kt++) {
        cp_wait0();
        __syncthreads();
        if (kt + 1 <= qt) issue(kt + 1, st ^ 1);

        float* ks = sm + st * STAGE;
        float* vs = ks + 64 * PAD;

        // S = Q @ K^T
        float S[8][4];
        #pragma unroll
        for (int j = 0; j < 8; j++)
            #pragma unroll
            for (int i = 0; i < 4; i++) S[j][i] = 0.f;

        #pragma unroll
        for (int s = 0; s < 8; s++) {
            #pragma unroll
            for (int j = 0; j < 8; j++) {
                const float* bp = &ks[(j * 8 + g) * PAD + s * 8 + tg];
                unsigned b0 = __float_as_uint(bp[0]);
                unsigned b1 = __float_as_uint(bp[4]);
                mma_tf32(S[j], qa[s][0], qa[s][1], qa[s][2], qa[s][3], b0, b1);
            }
        }
        __syncthreads();   // all S reads of ks done (P will overwrite it)

        // causal mask (diagonal tile only)
        if (kt == qt) {
            int r0 = 16 * w + g, r1 = r0 + 8;
            #pragma unroll
            for (int j = 0; j < 8; j++) {
                int c0 = j * 8 + 2 * tg, c1 = c0 + 1;
                if (c0 > r0) S[j][0] = -INFINITY;
                if (c1 > r0) S[j][1] = -INFINITY;
                if (c0 > r1) S[j][2] = -INFINITY;
                if (c1 > r1) S[j][3] = -INFINITY;
            }
        }

        // online softmax
        float tmax0 = -INFINITY, tmax1 = -INFINITY;
        #pragma unroll
        for (int j = 0; j < 8; j++) {
            tmax0 = fmaxf(tmax0, fmaxf(S[j][0], S[j][1]));
            tmax1 = fmaxf(tmax1, fmaxf(S[j][2], S[j][3]));
        }
        tmax0 = fmaxf(tmax0, __shfl_xor_sync(0xffffffffu, tmax0, 1));
        tmax0 = fmaxf(tmax0, __shfl_xor_sync(0xffffffffu, tmax0, 2));
        tmax1 = fmaxf(tmax1, __shfl_xor_sync(0xffffffffu, tmax1, 1));
        tmax1 = fmaxf(tmax1, __shfl_xor_sync(0xffffffffu, tmax1, 2));

        float mn0 = fmaxf(m0, tmax0), mn1 = fmaxf(m1, tmax1);
        float al0 = __expf(m0 - mn0), al1 = __expf(m1 - mn1);
        m0 = mn0; m1 = mn1;

        float rs0 = 0.f, rs1 = 0.f;
        #pragma unroll
        for (int j = 0; j < 8; j++) {
            S[j][0] = __expf(S[j][0] - mn0);
            S[j][1] = __expf(S[j][1] - mn0);
            S[j][2] = __expf(S[j][2] - mn1);
            S[j][3] = __expf(S[j][3] - mn1);
            rs0 += S[j][0] + S[j][1];
            rs1 += S[j][2] + S[j][3];
        }
        rs0 += __shfl_xor_sync(0xffffffffu, rs0, 1);
        rs0 += __shfl_xor_sync(0xffffffffu, rs0, 2);
        rs1 += __shfl_xor_sync(0xffffffffu, rs1, 1);
        rs1 += __shfl_xor_sync(0xffffffffu, rs1, 2);
        l0 = l0 * al0 + rs0;
        l1 = l1 * al1 + rs1;

        #pragma unroll
        for (int j = 0; j < 8; j++) {
            O[j][0] *= al0; O[j][1] *= al0;
            O[j][2] *= al1; O[j][3] *= al1;
        }

        // stage P (tf32) into the freed K buffer (warp-private rows)
        int pr0 = 16 * w + g, pr1 = pr0 + 8;
        #pragma unroll
        for (int j = 0; j < 8; j++) {
            int c = j * 8 + 2 * tg;
            ks[pr0 * PAD + c]     = __uint_as_float(f2tf32(S[j][0]));
            ks[pr0 * PAD + c + 1] = __uint_as_float(f2tf32(S[j][1]));
            ks[pr1 * PAD + c]     = __uint_as_float(f2tf32(S[j][2]));
            ks[pr1 * PAD + c + 1] = __uint_as_float(f2tf32(S[j][3]));
        }
        __syncwarp();

        // O += P @ V
        #pragma unroll
        for (int s = 0; s < 8; s++) {
            const float* pb = &ks[(16 * w + g) * PAD + s * 8 + tg];
            unsigned pa0 = __float_as_uint(pb[0]);
            unsigned pa1 = __float_as_uint(pb[8 * PAD]);
            unsigned pa2 = __float_as_uint(pb[4]);
            unsigned pa3 = __float_as_uint(pb[8 * PAD + 4]);
            #pragma unroll
            for (int j = 0; j < 8; j++) {
                const float* bp = &vs[(j * 8 + g) * PAD + s * 8 + tg];
                unsigned b0 = __float_as_uint(bp[0]);
                unsigned b1 = __float_as_uint(bp[4]);
                mma_tf32(O[j], pa0, pa1, pa2, pa3, b0, b1);
            }
        }
        st ^= 1;
    }

    float inv0 = 1.0f / l0, inv1 = 1.0f / l1;
    int r0 = qt * 64 + 16 * w + g;
    #pragma unroll
    for (int j = 0; j < 8; j++) {
        int col = j * 8 + 2 * tg;
        *(float2*)&out[((size_t)b * SEQ + r0) * HD + col] =
            make_float2(O[j][0] * inv0, O[j][1] * inv0);
        *(float2*)&out[((size_t)b * SEQ + r0 + 8) * HD + col] =
            make_float2(O[j][2] * inv1, O[j][3] * inv1);
    }
}

extern "C" void kernel_launch(void* const* d_in, const int* in_sizes, int n_in,
                              void* d_out, int out_size)
{
    const float* x  = (const float*)d_in[0];
    const float* Wq = (const float*)d_in[1];
    const float* bq = (const float*)d_in[2];
    const float* Wk = (const float*)d_in[3];
    const float* bk = (const float*)d_in[4];
    const float* Wv = (const float*)d_in[5];
    const float* bv = (const float*)d_in[6];
    float* out = (float*)d_out;

    const int qkv_smem  = 2 * 4 * 64 * PAD * sizeof(float);  // 139264
    const int attn_smem = 2 * 2 * 64 * PAD * sizeof(float);  // 69632
    cudaFuncSetAttribute(qkv_kernel,  cudaFuncAttributeMaxDynamicSharedMemorySize, qkv_smem);
    cudaFuncSetAttribute(attn_kernel, cudaFuncAttributeMaxDynamicSharedMemorySize, attn_smem);

    prep_w<<<(3 * EMB * HD + 255) / 256, 256>>>(Wq, Wk, Wv);
    qkv_kernel<<<(BATCH * SEQ) / 64, 384, qkv_smem>>>(x, bq, bk, bv);

    dim3 grid(SEQ / 64, BATCH);
    attn_kernel<<<grid, 128, attn_smem>>>(out);
}

// round 4
// speedup vs baseline: 4.3789x; 1.3296x over previous
#include <cuda_runtime.h>
#include <cuda_fp16.h>
#include <math.h>

#define BATCH 8
#define SEQ   4096
#define EMB   768
#define HD    64
#define PADF  68    // float smem row stride (x tiles)
#define STH   72    // half smem row stride (64 data + 8 pad), 144B, 16B-aligned

// fp16 scratch
__device__ __half g_q [BATCH * SEQ * HD];   // [b][t][d], pre-scaled by 0.125*log2(e)
__device__ __half g_k [BATCH * SEQ * HD];   // [b][t][d]
__device__ __half g_vT[BATCH * HD * SEQ];   // [b][d][t]
__device__ __half g_wT[3 * HD * EMB];       // [m][n][k]

__device__ __forceinline__ void mma_f16(float c[4],
                                        unsigned a0, unsigned a1, unsigned a2, unsigned a3,
                                        unsigned b0, unsigned b1) {
    asm("mma.sync.aligned.m16n8k16.row.col.f32.f16.f16.f32 "
        "{%0,%1,%2,%3}, {%4,%5,%6,%7}, {%8,%9}, {%0,%1,%2,%3};"
        : "+f"(c[0]), "+f"(c[1]), "+f"(c[2]), "+f"(c[3])
        : "r"(a0), "r"(a1), "r"(a2), "r"(a3), "r"(b0), "r"(b1));
}

__device__ __forceinline__ void cp16(void* dst, const void* src) {
    unsigned d = (unsigned)__cvta_generic_to_shared(dst);
    asm volatile("cp.async.cg.shared.global [%0], [%1], 16;" :: "r"(d), "l"(src));
}
__device__ __forceinline__ void cp_commit() { asm volatile("cp.async.commit_group;"); }
__device__ __forceinline__ void cp_wait0()  { asm volatile("cp.async.wait_group 0;" ::: "memory"); }

__device__ __forceinline__ float ex2f(float x) {
    float y;
    asm("ex2.approx.ftz.f32 %0, %1;" : "=f"(y) : "f"(x));
    return y;
}
__device__ __forceinline__ unsigned h2u(__half2 h) { return *(unsigned*)&h; }

// ---------------------------------------------------------------------------
// Kernel 0: transpose + fp16-convert weights: g_wT[m][n][k]
// ---------------------------------------------------------------------------
__global__ __launch_bounds__(256) void prep_w(
    const float* __restrict__ Wq, const float* __restrict__ Wk, const float* __restrict__ Wv)
{
    int i = blockIdx.x * 256 + threadIdx.x;
    if (i >= 3 * EMB * HD) return;
    int m = i / (EMB * HD);
    int r = (i / HD) % EMB;
    int c = i & (HD - 1);
    const float* W = (m == 0) ? Wq : (m == 1) ? Wk : Wv;
    g_wT[(m * HD + c) * EMB + r] = __float2half(W[r * HD + c]);
}

// ---------------------------------------------------------------------------
// Kernel 1: fused QKV projection, fp16 MMA (m16n8k16), cp.async double-buffered.
// 384 threads = 12 warps; warp w: rows 16*(w&3), matrix (w>>2).
// ---------------------------------------------------------------------------
#define XBYTES (64 * PADF * 4)             // 17408
#define WBYTES (3 * 64 * STH * 2)          // 27648
#define QSTAGE (XBYTES + WBYTES)           // 45056

__global__ __launch_bounds__(384) void qkv_kernel(
    const float* __restrict__ x,
    const float* __restrict__ bq, const float* __restrict__ bk, const float* __restrict__ bv)
{
    extern __shared__ char smc[];

    const int tid  = threadIdx.x;
    const int lane = tid & 31;
    const int w    = tid >> 5;
    const int rg   = w & 3;
    const int mat  = w >> 2;
    const int g    = lane >> 2;
    const int tg   = lane & 3;
    const int row0 = blockIdx.x * 64;

    const float* bias = (mat == 0) ? bq : (mat == 1) ? bk : bv;

    auto issue = [&](int kt, int st) {
        float*  xs = (float*)(smc + st * QSTAGE);
        __half* ws = (__half*)(smc + st * QSTAGE + XBYTES);
        for (int i = tid; i < 64 * 16; i += 384) {      // x: 64 rows x 16 f32x4 chunks
            int r = i >> 4, q = i & 15;
            cp16(&xs[r * PADF + q * 4], &x[(size_t)(row0 + r) * EMB + kt * 64 + q * 4]);
        }
        for (int i = tid; i < 3 * 64 * 8; i += 384) {   // wT: 192 rows x 8 h16x8 chunks
            int r = i >> 3, q = i & 7;
            cp16(&ws[r * STH + q * 8], &g_wT[(size_t)r * EMB + kt * 64 + q * 8]);
        }
        cp_commit();
    };

    float acc[8][4];
    #pragma unroll
    for (int j = 0; j < 8; j++)
        #pragma unroll
        for (int i = 0; i < 4; i++) acc[j][i] = 0.f;

    issue(0, 0);
    int st = 0;
    for (int kt = 0; kt < EMB / 64; kt++) {
        cp_wait0();
        __syncthreads();
        if (kt + 1 < EMB / 64) issue(kt + 1, st ^ 1);

        float*  xs = (float*)(smc + st * QSTAGE);
        __half* ws = (__half*)(smc + st * QSTAGE + XBYTES) + mat * 64 * STH;

        unsigned a[4][4];
        #pragma unroll
        for (int s = 0; s < 4; s++) {
            const float* base = &xs[(16 * rg + g) * PADF + 16 * s + 2 * tg];
            float2 f0 = *(const float2*)&base[0];
            float2 f1 = *(const float2*)&base[8 * PADF];
            float2 f2 = *(const float2*)&base[8];
            float2 f3 = *(const float2*)&base[8 * PADF + 8];
            a[s][0] = h2u(__floats2half2_rn(f0.x, f0.y));
            a[s][1] = h2u(__floats2half2_rn(f1.x, f1.y));
            a[s][2] = h2u(__floats2half2_rn(f2.x, f2.y));
            a[s][3] = h2u(__floats2half2_rn(f3.x, f3.y));
        }
        #pragma unroll
        for (int s = 0; s < 4; s++) {
            #pragma unroll
            for (int j = 0; j < 8; j++) {
                const __half* bp = &ws[(j * 8 + g) * STH + 16 * s + 2 * tg];
                unsigned b0 = *(const unsigned*)&bp[0];
                unsigned b1 = *(const unsigned*)&bp[8];
                mma_f16(acc[j], a[s][0], a[s][1], a[s][2], a[s][3], b0, b1);
            }
        }
        st ^= 1;
    }

    // epilogue
    const float QSCALE = 0.125f * 1.4426950408889634f;   // D^-0.5 * log2(e)
    #pragma unroll
    for (int j = 0; j < 8; j++) {
        int col = j * 8 + 2 * tg;
        float b0 = bias[col], b1 = bias[col + 1];
        int r0 = row0 + 16 * rg + g;
        float v00 = acc[j][0] + b0, v01 = acc[j][1] + b1;
        float v10 = acc[j][2] + b0, v11 = acc[j][3] + b1;
        if (mat == 0) { v00 *= QSCALE; v01 *= QSCALE; v10 *= QSCALE; v11 *= QSCALE; }
        if (mat == 2) {
            int b = r0 >> 12, t = r0 & (SEQ - 1);
            size_t base = (size_t)b * HD * SEQ;
            g_vT[base + (size_t)col       * SEQ + t]     = __float2half(v00);
            g_vT[base + (size_t)(col + 1) * SEQ + t]     = __float2half(v01);
            g_vT[base + (size_t)col       * SEQ + t + 8] = __float2half(v10);
            g_vT[base + (size_t)(col + 1) * SEQ + t + 8] = __float2half(v11);
        } else {
            __half* outp = (mat == 0) ? g_q : g_k;
            *(__half2*)&outp[(size_t)r0 * HD + col]       = __floats2half2_rn(v00, v01);
            *(__half2*)&outp[(size_t)(r0 + 8) * HD + col] = __floats2half2_rn(v10, v11);
        }
    }
}

// ---------------------------------------------------------------------------
// Kernel 2: causal flash attention, fp16 MMA, 128-query tiles, 8 warps.
// K/V double-buffered via cp.async; softmax in log2 domain (q pre-scaled).
// ---------------------------------------------------------------------------
#define ASTAGE (2 * 64 * STH)    // halves per stage (K tile + V tile)

__global__ __launch_bounds__(256) void attn_kernel(float* __restrict__ out)
{
    extern __shared__ __half smh[];
    __half* p_sh = smh + 2 * ASTAGE;   // [128][STH] P staging (warp-private rows)

    const int tid  = threadIdx.x;
    const int lane = tid & 31;
    const int w    = tid >> 5;         // 0..7, rows 16w..16w+15
    const int g    = lane >> 2;
    const int tg   = lane & 3;
    const int qt   = gridDim.x - 1 - blockIdx.x;   // heaviest first
    const int b    = blockIdx.y;
    const int nkt  = 2 * qt + 2;       // key tiles

    const __half* qg  = g_q  + ((size_t)b * SEQ + qt * 128) * HD;
    const __half* kg  = g_k  + (size_t)b * SEQ * HD;
    const __half* vTg = g_vT + (size_t)b * HD * SEQ;

    auto issue = [&](int kt, int stg) {
        __half* ks = smh + stg * ASTAGE;
        __half* vs = ks + 64 * STH;
        for (int i = tid; i < 64 * 8; i += 256) {
            int r = i >> 3, q = i & 7;
            cp16(&ks[r * STH + q * 8], &kg[(size_t)(kt * 64 + r) * HD + q * 8]);
            cp16(&vs[r * STH + q * 8], &vTg[(size_t)r * SEQ + kt * 64 + q * 8]);
        }
        cp_commit();
    };

    issue(0, 0);

    // Q fragments from global (fp16, pre-scaled, log2 domain)
    unsigned qa[4][4];
    #pragma unroll
    for (int s = 0; s < 4; s++) {
        const __half* base = &qg[(size_t)(16 * w + g) * HD + 16 * s + 2 * tg];
        qa[s][0] = *(const unsigned*)&base[0];
        qa[s][1] = *(const unsigned*)&base[8 * HD];
        qa[s][2] = *(const unsigned*)&base[8];
        qa[s][3] = *(const unsigned*)&base[8 * HD + 8];
    }

    float O[8][4];
    #pragma unroll
    for (int j = 0; j < 8; j++)
        #pragma unroll
        for (int i = 0; i < 4; i++) O[j][i] = 0.f;
    float m0 = -INFINITY, m1 = -INFINITY, l0 = 0.f, l1 = 0.f;

    int st = 0;
    for (int kt = 0; kt < nkt; kt++) {
        cp_wait0();
        __syncthreads();
        if (kt + 1 < nkt) issue(kt + 1, st ^ 1);

        __half* ks = smh + st * ASTAGE;
        __half* vs = ks + 64 * STH;

        // S = Q @ K^T  (log2 domain)
        float S[8][4];
        #pragma unroll
        for (int j = 0; j < 8; j++)
            #pragma unroll
            for (int i = 0; i < 4; i++) S[j][i] = 0.f;

        #pragma unroll
        for (int s = 0; s < 4; s++) {
            #pragma unroll
            for (int j = 0; j < 8; j++) {
                const __half* bp = &ks[(j * 8 + g) * STH + 16 * s + 2 * tg];
                unsigned b0 = *(const unsigned*)&bp[0];
                unsigned b1 = *(const unsigned*)&bp[8];
                mma_f16(S[j], qa[s][0], qa[s][1], qa[s][2], qa[s][3], b0, b1);
            }
        }

        // causal mask — only the last two key tiles intersect the diagonal
        if (kt >= 2 * qt) {
            int kb = (kt - 2 * qt) * 64;
            int r0 = 16 * w + g, r1 = r0 + 8;
            #pragma unroll
            for (int j = 0; j < 8; j++) {
                int c0 = kb + j * 8 + 2 * tg, c1 = c0 + 1;
                if (c0 > r0) S[j][0] = -INFINITY;
                if (c1 > r0) S[j][1] = -INFINITY;
                if (c0 > r1) S[j][2] = -INFINITY;
                if (c1 > r1) S[j][3] = -INFINITY;
            }
        }

        // online softmax (base-2)
        float tmax0 = -INFINITY, tmax1 = -INFINITY;
        #pragma unroll
        for (int j = 0; j < 8; j++) {
            tmax0 = fmaxf(tmax0, fmaxf(S[j][0], S[j][1]));
            tmax1 = fmaxf(tmax1, fmaxf(S[j][2], S[j][3]));
        }
        tmax0 = fmaxf(tmax0, __shfl_xor_sync(0xffffffffu, tmax0, 1));
        tmax0 = fmaxf(tmax0, __shfl_xor_sync(0xffffffffu, tmax0, 2));
        tmax1 = fmaxf(tmax1, __shfl_xor_sync(0xffffffffu, tmax1, 1));
        tmax1 = fmaxf(tmax1, __shfl_xor_sync(0xffffffffu, tmax1, 2));

        float mn0 = fmaxf(m0, tmax0), mn1 = fmaxf(m1, tmax1);
        float al0 = ex2f(m0 - mn0), al1 = ex2f(m1 - mn1);
        m0 = mn0; m1 = mn1;

        float rs0 = 0.f, rs1 = 0.f;
        #pragma unroll
        for (int j = 0; j < 8; j++) {
            S[j][0] = ex2f(S[j][0] - mn0);
            S[j][1] = ex2f(S[j][1] - mn0);
            S[j][2] = ex2f(S[j][2] - mn1);
            S[j][3] = ex2f(S[j][3] - mn1);
            rs0 += S[j][0] + S[j][1];
            rs1 += S[j][2] + S[j][3];
        }
        rs0 += __shfl_xor_sync(0xffffffffu, rs0, 1);
        rs0 += __shfl_xor_sync(0xffffffffu, rs0, 2);
        rs1 += __shfl_xor_sync(0xffffffffu, rs1, 1);
        rs1 += __shfl_xor_sync(0xffffffffu, rs1, 2);
        l0 = l0 * al0 + rs0;
        l1 = l1 * al1 + rs1;

        #pragma unroll
        for (int j = 0; j < 8; j++) {
            O[j][0] *= al0; O[j][1] *= al0;
            O[j][2] *= al1; O[j][3] *= al1;
        }

        // stage P as fp16 (warp-private rows)
        int pr0 = 16 * w + g, pr1 = pr0 + 8;
        #pragma unroll
        for (int j = 0; j < 8; j++) {
            int c = j * 8 + 2 * tg;
            *(__half2*)&p_sh[pr0 * STH + c] = __floats2half2_rn(S[j][0], S[j][1]);
            *(__half2*)&p_sh[pr1 * STH + c] = __floats2half2_rn(S[j][2], S[j][3]);
        }
        __syncwarp();

        // O += P @ V
        #pragma unroll
        for (int s = 0; s < 4; s++) {
            const __half* pb = &p_sh[(16 * w + g) * STH + 16 * s + 2 * tg];
            unsigned pa0 = *(const unsigned*)&pb[0];
            unsigned pa1 = *(const unsigned*)&pb[8 * STH];
            unsigned pa2 = *(const unsigned*)&pb[8];
            unsigned pa3 = *(const unsigned*)&pb[8 * STH + 8];
            #pragma unroll
            for (int j = 0; j < 8; j++) {
                const __half* bp = &vs[(j * 8 + g) * STH + 16 * s + 2 * tg];
                unsigned b0 = *(const unsigned*)&bp[0];
                unsigned b1 = *(const unsigned*)&bp[8];
                mma_f16(O[j], pa0, pa1, pa2, pa3, b0, b1);
            }
        }
        st ^= 1;
    }

    float inv0 = 1.0f / l0, inv1 = 1.0f / l1;
    int r0 = qt * 128 + 16 * w + g;
    #pragma unroll
    for (int j = 0; j < 8; j++) {
        int col = j * 8 + 2 * tg;
        *(float2*)&out[((size_t)b * SEQ + r0) * HD + col] =
            make_float2(O[j][0] * inv0, O[j][1] * inv0);
        *(float2*)&out[((size_t)b * SEQ + r0 + 8) * HD + col] =
            make_float2(O[j][2] * inv1, O[j][3] * inv1);
    }
}

extern "C" void kernel_launch(void* const* d_in, const int* in_sizes, int n_in,
                              void* d_out, int out_size)
{
    const float* x  = (const float*)d_in[0];
    const float* Wq = (const float*)d_in[1];
    const float* bq = (const float*)d_in[2];
    const float* Wk = (const float*)d_in[3];
    const float* bk = (const float*)d_in[4];
    const float* Wv = (const float*)d_in[5];
    const float* bv = (const float*)d_in[6];
    float* out = (float*)d_out;

    const int qkv_smem  = 2 * QSTAGE;                                   // 90112
    const int attn_smem = (2 * ASTAGE + 128 * STH) * (int)sizeof(__half); // 55296
    cudaFuncSetAttribute(qkv_kernel,  cudaFuncAttributeMaxDynamicSharedMemorySize, qkv_smem);
    cudaFuncSetAttribute(attn_kernel, cudaFuncAttributeMaxDynamicSharedMemorySize, attn_smem);

    prep_w<<<(3 * EMB * HD + 255) / 256, 256>>>(Wq, Wk, Wv);
    qkv_kernel<<<(BATCH * SEQ) / 64, 384, qkv_smem>>>(x, bq, bk, bv);

    dim3 grid(SEQ / 128, BATCH);
    attn_kernel<<<grid, 256, attn_smem>>>(out);
}

// round 6
// speedup vs baseline: 4.8614x; 1.1102x over previous
#include <cuda_runtime.h>
#include <cuda_fp16.h>
#include <math.h>

#define BATCH 8
#define SEQ   4096
#define EMB   768
#define HD    64
#define PADF  68    // float smem row stride (x tiles)
#define STH   72    // half smem row stride (64 data + 8 pad), 144B, 16B-aligned

// fp16 scratch
__device__ __half g_q [BATCH * SEQ * HD];   // [b][t][d], pre-scaled by 0.125*log2(e)
__device__ __half g_k [BATCH * SEQ * HD];   // [b][t][d]
__device__ __half g_vT[BATCH * HD * SEQ];   // [b][d][t]
__device__ __half g_wT[3 * HD * EMB];       // [m][n][k]

__device__ __forceinline__ void mma_f16(float c[4],
                                        unsigned a0, unsigned a1, unsigned a2, unsigned a3,
                                        unsigned b0, unsigned b1) {
    asm("mma.sync.aligned.m16n8k16.row.col.f32.f16.f16.f32 "
        "{%0,%1,%2,%3}, {%4,%5,%6,%7}, {%8,%9}, {%0,%1,%2,%3};"
        : "+f"(c[0]), "+f"(c[1]), "+f"(c[2]), "+f"(c[3])
        : "r"(a0), "r"(a1), "r"(a2), "r"(a3), "r"(b0), "r"(b1));
}

__device__ __forceinline__ void cp16(void* dst, const void* src) {
    unsigned d = (unsigned)__cvta_generic_to_shared(dst);
    asm volatile("cp.async.cg.shared.global [%0], [%1], 16;" :: "r"(d), "l"(src));
}
__device__ __forceinline__ void cp_commit() { asm volatile("cp.async.commit_group;"); }
__device__ __forceinline__ void cp_wait0()  { asm volatile("cp.async.wait_group 0;" ::: "memory"); }

__device__ __forceinline__ float ex2f(float x) {
    float y;
    asm("ex2.approx.ftz.f32 %0, %1;" : "=f"(y) : "f"(x));
    return y;
}
__device__ __forceinline__ unsigned h2u(__half2 h) { return *(unsigned*)&h; }

// ---------------------------------------------------------------------------
// Kernel 0: transpose + fp16-convert weights: g_wT[m][n][k]
// ---------------------------------------------------------------------------
__global__ __launch_bounds__(256) void prep_w(
    const float* __restrict__ Wq, const float* __restrict__ Wk, const float* __restrict__ Wv)
{
    int i = blockIdx.x * 256 + threadIdx.x;
    if (i >= 3 * EMB * HD) return;
    int m = i / (EMB * HD);
    int r = (i / HD) % EMB;
    int c = i & (HD - 1);
    const float* W = (m == 0) ? Wq : (m == 1) ? Wk : Wv;
    g_wT[(m * HD + c) * EMB + r] = __float2half(W[r * HD + c]);
}

// ---------------------------------------------------------------------------
// Kernel 1: fused QKV projection, fp16 MMA (m16n8k16), cp.async double-buffered.
// 384 threads = 12 warps; warp w: rows 16*(w&3), matrix (w>>2).
// ---------------------------------------------------------------------------
#define XBYTES (64 * PADF * 4)             // 17408
#define WBYTES (3 * 64 * STH * 2)          // 27648
#define QSTAGE (XBYTES + WBYTES)           // 45056

__global__ __launch_bounds__(384) void qkv_kernel(
    const float* __restrict__ x,
    const float* __restrict__ bq, const float* __restrict__ bk, const float* __restrict__ bv)
{
    extern __shared__ char smc[];

    const int tid  = threadIdx.x;
    const int lane = tid & 31;
    const int w    = tid >> 5;
    const int rg   = w & 3;
    const int mat  = w >> 2;
    const int g    = lane >> 2;
    const int tg   = lane & 3;
    const int row0 = blockIdx.x * 64;

    const float* bias = (mat == 0) ? bq : (mat == 1) ? bk : bv;

    auto issue = [&](int kt, int st) {
        float*  xs = (float*)(smc + st * QSTAGE);
        __half* ws = (__half*)(smc + st * QSTAGE + XBYTES);
        for (int i = tid; i < 64 * 16; i += 384) {
            int r = i >> 4, q = i & 15;
            cp16(&xs[r * PADF + q * 4], &x[(size_t)(row0 + r) * EMB + kt * 64 + q * 4]);
        }
        for (int i = tid; i < 3 * 64 * 8; i += 384) {
            int r = i >> 3, q = i & 7;
            cp16(&ws[r * STH + q * 8], &g_wT[(size_t)r * EMB + kt * 64 + q * 8]);
        }
        cp_commit();
    };

    float acc[8][4];
    #pragma unroll
    for (int j = 0; j < 8; j++)
        #pragma unroll
        for (int i = 0; i < 4; i++) acc[j][i] = 0.f;

    issue(0, 0);
    int st = 0;
    for (int kt = 0; kt < EMB / 64; kt++) {
        cp_wait0();
        __syncthreads();
        if (kt + 1 < EMB / 64) issue(kt + 1, st ^ 1);

        float*  xs = (float*)(smc + st * QSTAGE);
        __half* ws = (__half*)(smc + st * QSTAGE + XBYTES) + mat * 64 * STH;

        unsigned a[4][4];
        #pragma unroll
        for (int s = 0; s < 4; s++) {
            const float* base = &xs[(16 * rg + g) * PADF + 16 * s + 2 * tg];
            float2 f0 = *(const float2*)&base[0];
            float2 f1 = *(const float2*)&base[8 * PADF];
            float2 f2 = *(const float2*)&base[8];
            float2 f3 = *(const float2*)&base[8 * PADF + 8];
            a[s][0] = h2u(__floats2half2_rn(f0.x, f0.y));
            a[s][1] = h2u(__floats2half2_rn(f1.x, f1.y));
            a[s][2] = h2u(__floats2half2_rn(f2.x, f2.y));
            a[s][3] = h2u(__floats2half2_rn(f3.x, f3.y));
        }
        #pragma unroll
        for (int s = 0; s < 4; s++) {
            #pragma unroll
            for (int j = 0; j < 8; j++) {
                const __half* bp = &ws[(j * 8 + g) * STH + 16 * s + 2 * tg];
                unsigned b0 = *(const unsigned*)&bp[0];
                unsigned b1 = *(const unsigned*)&bp[8];
                mma_f16(acc[j], a[s][0], a[s][1], a[s][2], a[s][3], b0, b1);
            }
        }
        st ^= 1;
    }

    const float QSCALE = 0.125f * 1.4426950408889634f;   // D^-0.5 * log2(e)
    #pragma unroll
    for (int j = 0; j < 8; j++) {
        int col = j * 8 + 2 * tg;
        float b0 = bias[col], b1 = bias[col + 1];
        int r0 = row0 + 16 * rg + g;
        float v00 = acc[j][0] + b0, v01 = acc[j][1] + b1;
        float v10 = acc[j][2] + b0, v11 = acc[j][3] + b1;
        if (mat == 0) { v00 *= QSCALE; v01 *= QSCALE; v10 *= QSCALE; v11 *= QSCALE; }
        if (mat == 2) {
            int b = r0 >> 12, t = r0 & (SEQ - 1);
            size_t base = (size_t)b * HD * SEQ;
            g_vT[base + (size_t)col       * SEQ + t]     = __float2half(v00);
            g_vT[base + (size_t)(col + 1) * SEQ + t]     = __float2half(v01);
            g_vT[base + (size_t)col       * SEQ + t + 8] = __float2half(v10);
            g_vT[base + (size_t)(col + 1) * SEQ + t + 8] = __float2half(v11);
        } else {
            __half* outp = (mat == 0) ? g_q : g_k;
            *(__half2*)&outp[(size_t)r0 * HD + col]       = __floats2half2_rn(v00, v01);
            *(__half2*)&outp[(size_t)(r0 + 8) * HD + col] = __floats2half2_rn(v10, v11);
        }
    }
}

// ---------------------------------------------------------------------------
// Kernel 2: causal flash attention, fp16 MMA, 128-query tiles, 8 warps.
// P kept entirely in registers (accumulator->A-fragment identity), K/V
// double-buffered via cp.async; softmax in log2 domain (q pre-scaled).
// __launch_bounds__(256, 2): cap regs at 128 so 2 CTAs co-reside per SM.
// ---------------------------------------------------------------------------
#define ASTAGE (2 * 64 * STH)    // halves per stage (K tile + V tile)

__global__ __launch_bounds__(256, 2) void attn_kernel(float* __restrict__ out)
{
    extern __shared__ __half smh[];

    const int tid  = threadIdx.x;
    const int lane = tid & 31;
    const int w    = tid >> 5;         // 0..7, rows 16w..16w+15
    const int g    = lane >> 2;
    const int tg   = lane & 3;
    const int qt   = gridDim.x - 1 - blockIdx.x;   // heaviest first
    const int b    = blockIdx.y;
    const int nkt  = 2 * qt + 2;       // key tiles of 64

    const __half* qg  = g_q  + ((size_t)b * SEQ + qt * 128) * HD;
    const __half* kg  = g_k  + (size_t)b * SEQ * HD;
    const __half* vTg = g_vT + (size_t)b * HD * SEQ;

    auto issue = [&](int kt, int stg) {
        __half* ks = smh + stg * ASTAGE;
        __half* vs = ks + 64 * STH;
        for (int i = tid; i < 64 * 8; i += 256) {
            int r = i >> 3, q = i & 7;
            cp16(&ks[r * STH + q * 8], &kg[(size_t)(kt * 64 + r) * HD + q * 8]);
            cp16(&vs[r * STH + q * 8], &vTg[(size_t)r * SEQ + kt * 64 + q * 8]);
        }
        cp_commit();
    };

    issue(0, 0);

    // Q fragments from global (fp16, pre-scaled, log2 domain)
    unsigned qa[4][4];
    #pragma unroll
    for (int s = 0; s < 4; s++) {
        const __half* base = &qg[(size_t)(16 * w + g) * HD + 16 * s + 2 * tg];
        qa[s][0] = *(const unsigned*)&base[0];
        qa[s][1] = *(const unsigned*)&base[8 * HD];
        qa[s][2] = *(const unsigned*)&base[8];
        qa[s][3] = *(const unsigned*)&base[8 * HD + 8];
    }

    float O[8][4];
    #pragma unroll
    for (int j = 0; j < 8; j++)
        #pragma unroll
        for (int i = 0; i < 4; i++) O[j][i] = 0.f;
    float m0 = -INFINITY, m1 = -INFINITY, l0 = 0.f, l1 = 0.f;

    int st = 0;
    for (int kt = 0; kt < nkt; kt++) {
        cp_wait0();
        __syncthreads();
        if (kt + 1 < nkt) issue(kt + 1, st ^ 1);

        __half* ks = smh + st * ASTAGE;
        __half* vs = ks + 64 * STH;

        // S = Q @ K^T  (log2 domain)
        float S[8][4];
        #pragma unroll
        for (int j = 0; j < 8; j++)
            #pragma unroll
            for (int i = 0; i < 4; i++) S[j][i] = 0.f;

        #pragma unroll
        for (int s = 0; s < 4; s++) {
            #pragma unroll
            for (int j = 0; j < 8; j++) {
                const __half* bp = &ks[(j * 8 + g) * STH + 16 * s + 2 * tg];
                unsigned b0 = *(const unsigned*)&bp[0];
                unsigned b1 = *(const unsigned*)&bp[8];
                mma_f16(S[j], qa[s][0], qa[s][1], qa[s][2], qa[s][3], b0, b1);
            }
        }

        // causal mask — only the last two key tiles intersect the diagonal
        if (kt >= 2 * qt) {
            int kb = (kt - 2 * qt) * 64;
            int r0 = 16 * w + g, r1 = r0 + 8;
            #pragma unroll
            for (int j = 0; j < 8; j++) {
                int c0 = kb + j * 8 + 2 * tg, c1 = c0 + 1;
                if (c0 > r0) S[j][0] = -INFINITY;
                if (c1 > r0) S[j][1] = -INFINITY;
                if (c0 > r1) S[j][2] = -INFINITY;
                if (c1 > r1) S[j][3] = -INFINITY;
            }
        }

        // online softmax (base-2); rows: r0 = 16w+g (S[j][0,1]), r1 = r0+8 (S[j][2,3])
        float tmax0 = -INFINITY, tmax1 = -INFINITY;
        #pragma unroll
        for (int j = 0; j < 8; j++) {
            tmax0 = fmaxf(tmax0, fmaxf(S[j][0], S[j][1]));
            tmax1 = fmaxf(tmax1, fmaxf(S[j][2], S[j][3]));
        }
        tmax0 = fmaxf(tmax0, __shfl_xor_sync(0xffffffffu, tmax0, 1));
        tmax0 = fmaxf(tmax0, __shfl_xor_sync(0xffffffffu, tmax0, 2));
        tmax1 = fmaxf(tmax1, __shfl_xor_sync(0xffffffffu, tmax1, 1));
        tmax1 = fmaxf(tmax1, __shfl_xor_sync(0xffffffffu, tmax1, 2));

        float mn0 = fmaxf(m0, tmax0), mn1 = fmaxf(m1, tmax1);
        float al0 = ex2f(m0 - mn0), al1 = ex2f(m1 - mn1);
        m0 = mn0; m1 = mn1;

        // exp + pack P directly into A-operand fragments (FA2 identity):
        //   pk[s][0] = P(row g,   keys 16s+2tg..+1)  = pack(S[2s][0],  S[2s][1])
        //   pk[s][1] = P(row g+8, keys 16s+2tg..+1)  = pack(S[2s][2],  S[2s][3])
        //   pk[s][2] = P(row g,   keys 16s+8+2tg..)  = pack(S[2s+1][0],S[2s+1][1])
        //   pk[s][3] = P(row g+8, keys 16s+8+2tg..)  = pack(S[2s+1][2],S[2s+1][3])
        float rs0 = 0.f, rs1 = 0.f;
        unsigned pk[4][4];
        #pragma unroll
        for (int s = 0; s < 4; s++) {
            float e00 = ex2f(S[2 * s][0] - mn0);
            float e01 = ex2f(S[2 * s][1] - mn0);
            float e02 = ex2f(S[2 * s][2] - mn1);
            float e03 = ex2f(S[2 * s][3] - mn1);
            float e10 = ex2f(S[2 * s + 1][0] - mn0);
            float e11 = ex2f(S[2 * s + 1][1] - mn0);
            float e12 = ex2f(S[2 * s + 1][2] - mn1);
            float e13 = ex2f(S[2 * s + 1][3] - mn1);
            rs0 += (e00 + e01) + (e10 + e11);
            rs1 += (e02 + e03) + (e12 + e13);
            pk[s][0] = h2u(__floats2half2_rn(e00, e01));
            pk[s][1] = h2u(__floats2half2_rn(e02, e03));
            pk[s][2] = h2u(__floats2half2_rn(e10, e11));
            pk[s][3] = h2u(__floats2half2_rn(e12, e13));
        }
        rs0 += __shfl_xor_sync(0xffffffffu, rs0, 1);
        rs0 += __shfl_xor_sync(0xffffffffu, rs0, 2);
        rs1 += __shfl_xor_sync(0xffffffffu, rs1, 1);
        rs1 += __shfl_xor_sync(0xffffffffu, rs1, 2);
        l0 = l0 * al0 + rs0;
        l1 = l1 * al1 + rs1;

        #pragma unroll
        for (int j = 0; j < 8; j++) {
            O[j][0] *= al0; O[j][1] *= al0;
            O[j][2] *= al1; O[j][3] *= al1;
        }

        // O += P @ V  (A = pk registers, B = V^T[d][key] in smem)
        #pragma unroll
        for (int s = 0; s < 4; s++) {
            #pragma unroll
            for (int j = 0; j < 8; j++) {
                const __half* bp = &vs[(j * 8 + g) * STH + 16 * s + 2 * tg];
                unsigned b0 = *(const unsigned*)&bp[0];
                unsigned b1 = *(const unsigned*)&bp[8];
                mma_f16(O[j], pk[s][0], pk[s][1], pk[s][2], pk[s][3], b0, b1);
            }
        }
        st ^= 1;
    }

    float inv0 = 1.0f / l0, inv1 = 1.0f / l1;
    int r0 = qt * 128 + 16 * w + g;
    #pragma unroll
    for (int j = 0; j < 8; j++) {
        int col = j * 8 + 2 * tg;
        *(float2*)&out[((size_t)b * SEQ + r0) * HD + col] =
            make_float2(O[j][0] * inv0, O[j][1] * inv0);
        *(float2*)&out[((size_t)b * SEQ + r0 + 8) * HD + col] =
            make_float2(O[j][2] * inv1, O[j][3] * inv1);
    }
}

extern "C" void kernel_launch(void* const* d_in, const int* in_sizes, int n_in,
                              void* d_out, int out_size)
{
    const float* x  = (const float*)d_in[0];
    const float* Wq = (const float*)d_in[1];
    const float* bq = (const float*)d_in[2];
    const float* Wk = (const float*)d_in[3];
    const float* bk = (const float*)d_in[4];
    const float* Wv = (const float*)d_in[5];
    const float* bv = (const float*)d_in[6];
    float* out = (float*)d_out;

    const int qkv_smem  = 2 * QSTAGE;                              // 90112
    const int attn_smem = 2 * ASTAGE * (int)sizeof(__half);        // 36864
    cudaFuncSetAttribute(qkv_kernel,  cudaFuncAttributeMaxDynamicSharedMemorySize, qkv_smem);
    cudaFuncSetAttribute(attn_kernel, cudaFuncAttributeMaxDynamicSharedMemorySize, attn_smem);

    prep_w<<<(3 * EMB * HD + 255) / 256, 256>>>(Wq, Wk, Wv);
    qkv_kernel<<<(BATCH * SEQ) / 64, 384, qkv_smem>>>(x, bq, bk, bv);

    dim3 grid(SEQ / 128, BATCH);
    attn_kernel<<<grid, 256, attn_smem>>>(out);
}

// round 7
// speedup vs baseline: 4.9452x; 1.0172x over previous
#include <cuda_runtime.h>
#include <cuda_fp16.h>
#include <math.h>

#define BATCH 8
#define SEQ   4096
#define EMB   768
#define HD    64
#define PADF  68    // float smem row stride (x tiles)
#define STH   72    // half smem row stride (64 data + 8 pad), 144B, 16B-aligned

// fp16 scratch
__device__ __half g_q [BATCH * SEQ * HD];   // [b][t][d], pre-scaled by 0.125*log2(e)
__device__ __half g_k [BATCH * SEQ * HD];   // [b][t][d]
__device__ __half g_vT[BATCH * HD * SEQ];   // [b][d][t]
__device__ __half g_wT[3 * HD * EMB];       // [m][n][k]

__device__ __forceinline__ void mma_f16(float c[4],
                                        unsigned a0, unsigned a1, unsigned a2, unsigned a3,
                                        unsigned b0, unsigned b1) {
    asm("mma.sync.aligned.m16n8k16.row.col.f32.f16.f16.f32 "
        "{%0,%1,%2,%3}, {%4,%5,%6,%7}, {%8,%9}, {%0,%1,%2,%3};"
        : "+f"(c[0]), "+f"(c[1]), "+f"(c[2]), "+f"(c[3])
        : "r"(a0), "r"(a1), "r"(a2), "r"(a3), "r"(b0), "r"(b1));
}

__device__ __forceinline__ void cp16(void* dst, const void* src) {
    unsigned d = (unsigned)__cvta_generic_to_shared(dst);
    asm volatile("cp.async.cg.shared.global [%0], [%1], 16;" :: "r"(d), "l"(src));
}
__device__ __forceinline__ void cp_commit() { asm volatile("cp.async.commit_group;"); }
__device__ __forceinline__ void cp_wait0()  { asm volatile("cp.async.wait_group 0;" ::: "memory"); }
__device__ __forceinline__ void cp_wait1()  { asm volatile("cp.async.wait_group 1;" ::: "memory"); }

__device__ __forceinline__ float ex2f(float x) {
    float y;
    asm("ex2.approx.ftz.f32 %0, %1;" : "=f"(y) : "f"(x));
    return y;
}
__device__ __forceinline__ unsigned h2u(__half2 h) { return *(unsigned*)&h; }

// ---------------------------------------------------------------------------
// Kernel 0: transpose + fp16-convert weights: g_wT[m][n][k]
// ---------------------------------------------------------------------------
__global__ __launch_bounds__(256) void prep_w(
    const float* __restrict__ Wq, const float* __restrict__ Wk, const float* __restrict__ Wv)
{
    int i = blockIdx.x * 256 + threadIdx.x;
    if (i >= 3 * EMB * HD) return;
    int m = i / (EMB * HD);
    int r = (i / HD) % EMB;
    int c = i & (HD - 1);
    const float* W = (m == 0) ? Wq : (m == 1) ? Wk : Wv;
    g_wT[(m * HD + c) * EMB + r] = __float2half(W[r * HD + c]);
}

// ---------------------------------------------------------------------------
// Kernel 1: fused QKV projection, fp16 MMA (m16n8k16), cp.async double-buffered.
// (unchanged from R6 — known good)
// ---------------------------------------------------------------------------
#define XBYTES (64 * PADF * 4)             // 17408
#define WBYTES (3 * 64 * STH * 2)          // 27648
#define QSTAGE (XBYTES + WBYTES)           // 45056

__global__ __launch_bounds__(384) void qkv_kernel(
    const float* __restrict__ x,
    const float* __restrict__ bq, const float* __restrict__ bk, const float* __restrict__ bv)
{
    extern __shared__ char smc[];

    const int tid  = threadIdx.x;
    const int lane = tid & 31;
    const int w    = tid >> 5;
    const int rg   = w & 3;
    const int mat  = w >> 2;
    const int g    = lane >> 2;
    const int tg   = lane & 3;
    const int row0 = blockIdx.x * 64;

    const float* bias = (mat == 0) ? bq : (mat == 1) ? bk : bv;

    auto issue = [&](int kt, int st) {
        float*  xs = (float*)(smc + st * QSTAGE);
        __half* ws = (__half*)(smc + st * QSTAGE + XBYTES);
        for (int i = tid; i < 64 * 16; i += 384) {
            int r = i >> 4, q = i & 15;
            cp16(&xs[r * PADF + q * 4], &x[(size_t)(row0 + r) * EMB + kt * 64 + q * 4]);
        }
        for (int i = tid; i < 3 * 64 * 8; i += 384) {
            int r = i >> 3, q = i & 7;
            cp16(&ws[r * STH + q * 8], &g_wT[(size_t)r * EMB + kt * 64 + q * 8]);
        }
        cp_commit();
    };

    float acc[8][4];
    #pragma unroll
    for (int j = 0; j < 8; j++)
        #pragma unroll
        for (int i = 0; i < 4; i++) acc[j][i] = 0.f;

    issue(0, 0);
    int st = 0;
    for (int kt = 0; kt < EMB / 64; kt++) {
        cp_wait0();
        __syncthreads();
        if (kt + 1 < EMB / 64) issue(kt + 1, st ^ 1);

        float*  xs = (float*)(smc + st * QSTAGE);
        __half* ws = (__half*)(smc + st * QSTAGE + XBYTES) + mat * 64 * STH;

        unsigned a[4][4];
        #pragma unroll
        for (int s = 0; s < 4; s++) {
            const float* base = &xs[(16 * rg + g) * PADF + 16 * s + 2 * tg];
            float2 f0 = *(const float2*)&base[0];
            float2 f1 = *(const float2*)&base[8 * PADF];
            float2 f2 = *(const float2*)&base[8];
            float2 f3 = *(const float2*)&base[8 * PADF + 8];
            a[s][0] = h2u(__floats2half2_rn(f0.x, f0.y));
            a[s][1] = h2u(__floats2half2_rn(f1.x, f1.y));
            a[s][2] = h2u(__floats2half2_rn(f2.x, f2.y));
            a[s][3] = h2u(__floats2half2_rn(f3.x, f3.y));
        }
        #pragma unroll
        for (int s = 0; s < 4; s++) {
            #pragma unroll
            for (int j = 0; j < 8; j++) {
                const __half* bp = &ws[(j * 8 + g) * STH + 16 * s + 2 * tg];
                unsigned b0 = *(const unsigned*)&bp[0];
                unsigned b1 = *(const unsigned*)&bp[8];
                mma_f16(acc[j], a[s][0], a[s][1], a[s][2], a[s][3], b0, b1);
            }
        }
        st ^= 1;
    }

    const float QSCALE = 0.125f * 1.4426950408889634f;   // D^-0.5 * log2(e)
    #pragma unroll
    for (int j = 0; j < 8; j++) {
        int col = j * 8 + 2 * tg;
        float b0 = bias[col], b1 = bias[col + 1];
        int r0 = row0 + 16 * rg + g;
        float v00 = acc[j][0] + b0, v01 = acc[j][1] + b1;
        float v10 = acc[j][2] + b0, v11 = acc[j][3] + b1;
        if (mat == 0) { v00 *= QSCALE; v01 *= QSCALE; v10 *= QSCALE; v11 *= QSCALE; }
        if (mat == 2) {
            int b = r0 >> 12, t = r0 & (SEQ - 1);
            size_t base = (size_t)b * HD * SEQ;
            g_vT[base + (size_t)col       * SEQ + t]     = __float2half(v00);
            g_vT[base + (size_t)(col + 1) * SEQ + t]     = __float2half(v01);
            g_vT[base + (size_t)col       * SEQ + t + 8] = __float2half(v10);
            g_vT[base + (size_t)(col + 1) * SEQ + t + 8] = __float2half(v11);
        } else {
            __half* outp = (mat == 0) ? g_q : g_k;
            *(__half2*)&outp[(size_t)r0 * HD + col]       = __floats2half2_rn(v00, v01);
            *(__half2*)&outp[(size_t)(r0 + 8) * HD + col] = __floats2half2_rn(v10, v11);
        }
    }
}

// ---------------------------------------------------------------------------
// Kernel 2: causal flash attention, fp16 MMA.
// 64-query tiles, 4 warps, 4 CTAs/SM; 3-stage cp.async pipeline (wait_group 1).
// qt assignment: orbit permutation so the 4 CTAs sharing one SM (bids k,
// k+148, k+296, k+444; stride 148 == 20 mod 64) have near-constant total work.
// ---------------------------------------------------------------------------
#define ASTAGE (2 * 64 * STH)    // halves per stage (K tile + V tile) = 18432 B

__global__ __launch_bounds__(128, 4) void attn_kernel(float* __restrict__ out)
{
    extern __shared__ __half smh[];

    const int tid  = threadIdx.x;
    const int lane = tid & 31;
    const int w    = tid >> 5;         // 0..3, query rows 16w..16w+15
    const int g    = lane >> 2;
    const int tg   = lane & 3;
    const int b    = blockIdx.y;

    // orbit permutation: x -> qt such that co-resident CTAs balance.
    // r = x&3 selects the orbit (stride 20 mod 64, gcd 4); q = x>>2 in [0,16);
    // orbit position p = 13*q mod 16 (13 = 5^-1 mod 16); alternate low/high.
    const int x  = blockIdx.x;
    const int r_ = x & 3;
    const int p  = (13 * (x >> 2)) & 15;
    const int a_ = r_ * 8 + (p >> 1);
    const int qt = (p & 1) ? (63 - a_) : a_;

    const int nkt = qt + 1;            // 64-key tiles

    const __half* qg  = g_q  + ((size_t)b * SEQ + qt * 64) * HD;
    const __half* kg  = g_k  + (size_t)b * SEQ * HD;
    const __half* vTg = g_vT + (size_t)b * HD * SEQ;

    auto issue = [&](int kt, int stg) {
        __half* ks = smh + stg * ASTAGE;
        __half* vs = ks + 64 * STH;
        for (int i = tid; i < 64 * 8; i += 128) {
            int r = i >> 3, q = i & 7;
            cp16(&ks[r * STH + q * 8], &kg[(size_t)(kt * 64 + r) * HD + q * 8]);
            cp16(&vs[r * STH + q * 8], &vTg[(size_t)r * SEQ + kt * 64 + q * 8]);
        }
        cp_commit();
    };

    issue(0, 0);
    issue(1 < nkt ? 1 : 0, 1);   // prefetch tile 1 (dup of 0 when qt==0; harmless)

    // Q fragments from global (fp16, pre-scaled, log2 domain)
    unsigned qa[4][4];
    #pragma unroll
    for (int s = 0; s < 4; s++) {
        const __half* base = &qg[(size_t)(16 * w + g) * HD + 16 * s + 2 * tg];
        qa[s][0] = *(const unsigned*)&base[0];
        qa[s][1] = *(const unsigned*)&base[8 * HD];
        qa[s][2] = *(const unsigned*)&base[8];
        qa[s][3] = *(const unsigned*)&base[8 * HD + 8];
    }

    float O[8][4];
    #pragma unroll
    for (int j = 0; j < 8; j++)
        #pragma unroll
        for (int i = 0; i < 4; i++) O[j][i] = 0.f;
    float m0 = -INFINITY, m1 = -INFINITY, l0 = 0.f, l1 = 0.f;

    for (int kt = 0; kt < nkt; kt++) {
        cp_wait1();                 // tile kt resident; tile kt+1 may still fly
        __syncthreads();
        if (kt + 2 < nkt) issue(kt + 2, (kt + 2) % 3);

        __half* ks = smh + (kt % 3) * ASTAGE;
        __half* vs = ks + 64 * STH;

        // S = Q @ K^T  (log2 domain)
        float S[8][4];
        #pragma unroll
        for (int j = 0; j < 8; j++)
            #pragma unroll
            for (int i = 0; i < 4; i++) S[j][i] = 0.f;

        #pragma unroll
        for (int s = 0; s < 4; s++) {
            #pragma unroll
            for (int j = 0; j < 8; j++) {
                const __half* bp = &ks[(j * 8 + g) * STH + 16 * s + 2 * tg];
                unsigned b0 = *(const unsigned*)&bp[0];
                unsigned b1 = *(const unsigned*)&bp[8];
                mma_f16(S[j], qa[s][0], qa[s][1], qa[s][2], qa[s][3], b0, b1);
            }
        }

        // causal mask (diagonal tile only)
        if (kt == qt) {
            int r0 = 16 * w + g, r1 = r0 + 8;
            #pragma unroll
            for (int j = 0; j < 8; j++) {
                int c0 = j * 8 + 2 * tg, c1 = c0 + 1;
                if (c0 > r0) S[j][0] = -INFINITY;
                if (c1 > r0) S[j][1] = -INFINITY;
                if (c0 > r1) S[j][2] = -INFINITY;
                if (c1 > r1) S[j][3] = -INFINITY;
            }
        }

        // online softmax (base-2)
        float tmax0 = -INFINITY, tmax1 = -INFINITY;
        #pragma unroll
        for (int j = 0; j < 8; j++) {
            tmax0 = fmaxf(tmax0, fmaxf(S[j][0], S[j][1]));
            tmax1 = fmaxf(tmax1, fmaxf(S[j][2], S[j][3]));
        }
        tmax0 = fmaxf(tmax0, __shfl_xor_sync(0xffffffffu, tmax0, 1));
        tmax0 = fmaxf(tmax0, __shfl_xor_sync(0xffffffffu, tmax0, 2));
        tmax1 = fmaxf(tmax1, __shfl_xor_sync(0xffffffffu, tmax1, 1));
        tmax1 = fmaxf(tmax1, __shfl_xor_sync(0xffffffffu, tmax1, 2));

        float mn0 = fmaxf(m0, tmax0), mn1 = fmaxf(m1, tmax1);
        float al0 = ex2f(m0 - mn0), al1 = ex2f(m1 - mn1);
        m0 = mn0; m1 = mn1;

        // exp + pack P directly into A-operand fragments (FA2 identity)
        float rs0 = 0.f, rs1 = 0.f;
        unsigned pk[4][4];
        #pragma unroll
        for (int s = 0; s < 4; s++) {
            float e00 = ex2f(S[2 * s][0] - mn0);
            float e01 = ex2f(S[2 * s][1] - mn0);
            float e02 = ex2f(S[2 * s][2] - mn1);
            float e03 = ex2f(S[2 * s][3] - mn1);
            float e10 = ex2f(S[2 * s + 1][0] - mn0);
            float e11 = ex2f(S[2 * s + 1][1] - mn0);
            float e12 = ex2f(S[2 * s + 1][2] - mn1);
            float e13 = ex2f(S[2 * s + 1][3] - mn1);
            rs0 += (e00 + e01) + (e10 + e11);
            rs1 += (e02 + e03) + (e12 + e13);
            pk[s][0] = h2u(__floats2half2_rn(e00, e01));
            pk[s][1] = h2u(__floats2half2_rn(e02, e03));
            pk[s][2] = h2u(__floats2half2_rn(e10, e11));
            pk[s][3] = h2u(__floats2half2_rn(e12, e13));
        }
        rs0 += __shfl_xor_sync(0xffffffffu, rs0, 1);
        rs0 += __shfl_xor_sync(0xffffffffu, rs0, 2);
        rs1 += __shfl_xor_sync(0xffffffffu, rs1, 1);
        rs1 += __shfl_xor_sync(0xffffffffu, rs1, 2);
        l0 = l0 * al0 + rs0;
        l1 = l1 * al1 + rs1;

        #pragma unroll
        for (int j = 0; j < 8; j++) {
            O[j][0] *= al0; O[j][1] *= al0;
            O[j][2] *= al1; O[j][3] *= al1;
        }

        // O += P @ V  (A = pk registers, B = V^T[d][key] in smem)
        #pragma unroll
        for (int s = 0; s < 4; s++) {
            #pragma unroll
            for (int j = 0; j < 8; j++) {
                const __half* bp = &vs[(j * 8 + g) * STH + 16 * s + 2 * tg];
                unsigned b0 = *(const unsigned*)&bp[0];
                unsigned b1 = *(const unsigned*)&bp[8];
                mma_f16(O[j], pk[s][0], pk[s][1], pk[s][2], pk[s][3], b0, b1);
            }
        }
    }

    float inv0 = 1.0f / l0, inv1 = 1.0f / l1;
    int r0 = qt * 64 + 16 * w + g;
    #pragma unroll
    for (int j = 0; j < 8; j++) {
        int col = j * 8 + 2 * tg;
        *(float2*)&out[((size_t)b * SEQ + r0) * HD + col] =
            make_float2(O[j][0] * inv0, O[j][1] * inv0);
        *(float2*)&out[((size_t)b * SEQ + r0 + 8) * HD + col] =
            make_float2(O[j][2] * inv1, O[j][3] * inv1);
    }
}

extern "C" void kernel_launch(void* const* d_in, const int* in_sizes, int n_in,
                              void* d_out, int out_size)
{
    const float* x  = (const float*)d_in[0];
    const float* Wq = (const float*)d_in[1];
    const float* bq = (const float*)d_in[2];
    const float* Wk = (const float*)d_in[3];
    const float* bk = (const float*)d_in[4];
    const float* Wv = (const float*)d_in[5];
    const float* bv = (const float*)d_in[6];
    float* out = (float*)d_out;

    const int qkv_smem  = 2 * QSTAGE;                              // 90112
    const int attn_smem = 3 * ASTAGE * (int)sizeof(__half);        // 55296
    cudaFuncSetAttribute(qkv_kernel,  cudaFuncAttributeMaxDynamicSharedMemorySize, qkv_smem);
    cudaFuncSetAttribute(attn_kernel, cudaFuncAttributeMaxDynamicSharedMemorySize, attn_smem);

    prep_w<<<(3 * EMB * HD + 255) / 256, 256>>>(Wq, Wk, Wv);
    qkv_kernel<<<(BATCH * SEQ) / 64, 384, qkv_smem>>>(x, bq, bk, bv);

    dim3 grid(SEQ / 64, BATCH);
    attn_kernel<<<grid, 128, attn_smem>>>(out);
}